// round 10
// baseline (speedup 1.0000x reference)
#include <cuda_runtime.h>
#include <cuda_fp16.h>
#include <math.h>

typedef unsigned long long u64;
typedef unsigned int u32;
typedef unsigned short u16;

// -------- prepped fragment-order weight streams (fp16 hi/lo, 2-term split) --------
__device__ __align__(128) unsigned char g_enc[393216];  // 12 chunks x 32KB, Ktilde=768
__device__ __align__(128) unsigned char g_ssm[327680];  // 10 chunks x 32KB, Ktilde=640
__device__ __align__(128) unsigned char g_cw[65536];    //  2 chunks x 32KB, Ktilde=512

__device__ __forceinline__ u16 hf_hi(float w) { return __half_as_ushort(__float2half_rn(w)); }
__device__ __forceinline__ u16 hf_lo(float w) {
    float h = __half2float(__float2half_rn(w));
    return __half_as_ushort(__float2half_rn(w - h));
}

// One thread per output fp16. Layout: chunk(32KB) -> slab(8KB enc/ssm, 2KB C) ->
// block(512B, (warp,mtile)) -> lane(16B) -> 4 regs x f16x2, matching the PTX
// m16n8k16 A-fragment: reg r holds (row + (r&1)*8, k + (r>>1)*8 + h).
__global__ void prep(const float* __restrict__ A_w, const float* __restrict__ B_w,
                     const float* __restrict__ C_w, const float* __restrict__ W_ih,
                     const float* __restrict__ W_hh) {
    u32 e = blockIdx.x * 256u + threadIdx.x;
    u32 kind, pos;
    if (e < 196608u)      { kind = 0; pos = e * 2u; }
    else if (e < 360448u) { kind = 1; pos = (e - 196608u) * 2u; }
    else if (e < 393216u) { kind = 2; pos = (e - 360448u) * 2u; }
    else return;
    u32 chunk = pos >> 15, inch = pos & 32767u;
    u32 slab, w, m, r3;
    if (kind < 2) { slab = inch >> 13; u32 r2 = inch & 8191u; u32 blk = r2 >> 9; w = blk >> 1; m = blk & 1u; r3 = r2 & 511u; }
    else          { slab = inch >> 11; u32 r2 = inch & 2047u; w = r2 >> 9; m = 0; r3 = r2 & 511u; }
    u32 t = r3 >> 4, r4 = r3 & 15u, reg = r4 >> 2, h = (r4 & 3u) >> 1;
    u32 row = (t >> 2) + (reg & 1u) * 8u;
    u32 kl  = (t & 3u) * 2u + (reg >> 1) * 8u + h;
    float src; u32 p;
    if (kind == 0) {
        u32 j = w * 32u + m * 16u + row;
        u32 kt = (chunk * 4u + slab) * 16u + kl;
        p = kt / 384u; u32 kk = kt % 384u;
        src = (kk < 128u) ? W_ih[j * 128u + kk] : W_hh[j * 256u + kk - 128u];
        *(u16*)(g_enc + pos) = p ? hf_lo(src) : hf_hi(src);
    } else if (kind == 1) {
        u32 j = w * 32u + m * 16u + row;
        u32 kt = (chunk * 4u + slab) * 16u + kl;
        p = kt / 320u; u32 kk = kt % 320u;
        src = (kk < 64u) ? B_w[j * 64u + kk] : A_w[j * 256u + kk - 64u];
        *(u16*)(g_ssm + pos) = p ? hf_lo(src) : hf_hi(src);
    } else {
        u32 o = w * 16u + row;
        u32 g4 = chunk * 16u + slab;
        p = g4 >> 4;
        u32 k = (g4 & 15u) * 16u + kl;        // 0..255
        src = C_w[o * 256u + k];
        *(u16*)(g_cw + pos) = p ? hf_lo(src) : hf_hi(src);
    }
}

// ---------------- PTX helpers ----------------
__device__ __forceinline__ u32 smem_u32(const void* p) {
    u32 a;
    asm("{ .reg .u64 t; cvta.to.shared.u64 t, %1; cvt.u32.u64 %0, t; }" : "=r"(a) : "l"(p));
    return a;
}
#define STS16(addr, v)  asm volatile("st.shared.u16 [%0], %1;" :: "r"(addr), "h"(v))
#define STS32(addr, f)  asm volatile("st.shared.f32 [%0], %1;" :: "r"(addr), "f"(f))
#define STSU32(addr, v) asm volatile("st.shared.u32 [%0], %1;" :: "r"(addr), "r"(v))
#define LDS32U(r, addr) asm volatile("ld.shared.u32 %0, [%1];" : "=r"(r) : "r"(addr))

#define MMA16816(c, a, b0, b1) \
    asm volatile("mma.sync.aligned.m16n8k16.row.col.f32.f16.f16.f32 " \
                 "{%0,%1,%2,%3},{%4,%5,%6,%7},{%8,%9},{%0,%1,%2,%3};" \
                 : "+f"((c)[0]), "+f"((c)[1]), "+f"((c)[2]), "+f"((c)[3]) \
                 : "r"((a)[0]), "r"((a)[1]), "r"((a)[2]), "r"((a)[3]), "r"(b0), "r"(b1))

__device__ __forceinline__ float my_tanh(float x) {
    float ax = fabsf(x);
    float e  = __expf(2.0f * ax);
    float r  = 1.0f - 2.0f / (e + 1.0f);
    return copysignf(r, x);
}

// ---------------- smem layout: U only ----------------
constexpr u32 UP = 1552;                 // U row pitch bytes (UP%128==16 -> conflict-free)
constexpr u32 OFF_U = 0;
constexpr u32 SMEM_TOTAL = 32 * UP;      // 49664

// dual-slot U write: hi at k, lo at k+P (Pb = part stride bytes)
__device__ __forceinline__ void put_duo(u32 ub, u32 k, float v, u32 Pb) {
    __half hb = __float2half_rn(v);
    u16 hi = __half_as_ushort(hb);
    u16 lo = __half_as_ushort(__float2half_rn(v - __half2float(hb)));
    u32 a = ub + k * 2u;
    STS16(a, hi); STS16(a + Pb, lo);
}

// stage 16 consecutive k-slots for one batch row: vector LDG + paired STS32
__device__ __forceinline__ void stage16(u32 ub, u32 k0, const float* s, u32 Pb) {
    float v[16];
    const float4* s4 = (const float4*)s;
#pragma unroll
    for (int q = 0; q < 4; q++) {
        float4 f = __ldg(s4 + q);
        v[q * 4] = f.x; v[q * 4 + 1] = f.y; v[q * 4 + 2] = f.z; v[q * 4 + 3] = f.w;
    }
#pragma unroll
    for (int i = 0; i < 16; i += 2) {
        __half a = __float2half_rn(v[i]), b = __float2half_rn(v[i + 1]);
        __half al = __float2half_rn(v[i] - __half2float(a));
        __half bl = __float2half_rn(v[i + 1] - __half2float(b));
        u32 hi = (u32)__half_as_ushort(a) | ((u32)__half_as_ushort(b) << 16);
        u32 lo = (u32)__half_as_ushort(al) | ((u32)__half_as_ushort(bl) << 16);
        u32 ad = ub + (k0 + (u32)i) * 2u;
        STSU32(ad, hi); STSU32(ad + Pb, lo);
    }
}
__device__ __forceinline__ void stage8(u32 ub, u32 k0, const float* s, u32 Pb) {
    float v[8];
    const float4* s4 = (const float4*)s;
#pragma unroll
    for (int q = 0; q < 2; q++) {
        float4 f = __ldg(s4 + q);
        v[q * 4] = f.x; v[q * 4 + 1] = f.y; v[q * 4 + 2] = f.z; v[q * 4 + 3] = f.w;
    }
#pragma unroll
    for (int i = 0; i < 8; i += 2) {
        __half a = __float2half_rn(v[i]), b = __float2half_rn(v[i + 1]);
        __half al = __float2half_rn(v[i] - __half2float(a));
        __half bl = __float2half_rn(v[i + 1] - __half2float(b));
        u32 hi = (u32)__half_as_ushort(a) | ((u32)__half_as_ushort(b) << 16);
        u32 lo = (u32)__half_as_ushort(al) | ((u32)__half_as_ushort(bl) << 16);
        u32 ad = ub + (k0 + (u32)i) * 2u;
        STSU32(ad, hi); STSU32(ad + Pb, lo);
    }
}

// main GEMM: A-frags via LDG.128 from L2-resident prepped stream with explicit
// chunk-level register double-buffering (8 LDGs in flight, one chunk of slack).
template <int NCH>
__device__ __forceinline__ void gemm_g(const unsigned char* __restrict__ gw,
                                       u32 SB, int warp, int lane,
                                       float acc[2][4][4]) {
    const u32 bB = SB + OFF_U + (u32)(lane >> 2) * UP + (u32)(lane & 3) * 4u;
    const uint4* __restrict__ ap =
        (const uint4*)(gw + (u32)(warp * 1024) + (u32)(lane * 16));
    uint4 Abuf[2][8];
#pragma unroll
    for (int sl = 0; sl < 4; sl++) {
        Abuf[0][sl * 2]     = __ldg(ap + sl * 512);
        Abuf[0][sl * 2 + 1] = __ldg(ap + sl * 512 + 32);
    }
    u32 kt = 0;
#pragma unroll 1
    for (int c = 0; c < NCH; c++) {
        if (c + 1 < NCH) {
            const uint4* np = ap + (c + 1) * 2048;
            uint4* nb = Abuf[(c + 1) & 1];
#pragma unroll
            for (int sl = 0; sl < 4; sl++) {
                nb[sl * 2]     = __ldg(np + sl * 512);
                nb[sl * 2 + 1] = __ldg(np + sl * 512 + 32);
            }
        }
        const uint4* A = Abuf[c & 1];
#pragma unroll
        for (int sl = 0; sl < 4; sl++) {
            u32 bk = bB + kt * 2u;
            u32 b0[4], b1[4];
#pragma unroll
            for (int nt = 0; nt < 4; nt++) {
                LDS32U(b0[nt], bk + (u32)nt * (8u * UP));
                LDS32U(b1[nt], bk + (u32)nt * (8u * UP) + 16u);
            }
            const u32* a0 = (const u32*)&A[sl * 2];
            const u32* a1 = (const u32*)&A[sl * 2 + 1];
#pragma unroll
            for (int nt = 0; nt < 4; nt++) {
                MMA16816(acc[0][nt], a0, b0[nt], b1[nt]);
                MMA16816(acc[1][nt], a1, b0[nt], b1[nt]);
            }
            kt += 16;
        }
    }
}

__global__ __launch_bounds__(256, 1) void ss_main(
    const float* __restrict__ pre_x, const float* __restrict__ pre_y,
    const float* __restrict__ fwd_x,
    const float* __restrict__ A_b, const float* __restrict__ B_b,
    const float* __restrict__ C_b, const float* __restrict__ b_ih,
    const float* __restrict__ b_hh, float* __restrict__ out)
{
    extern __shared__ char smraw[];
    const u32 SB = smem_u32(smraw);
    const int tid = threadIdx.x, lane = tid & 31, warp = tid >> 5;
    const int bbase = blockIdx.x * 32;
    const int gg = lane >> 2, tig = lane & 3;

    // zero U
    for (int i = tid; i < (int)(32 * UP / 4); i += 256) STS32(SB + OFF_U + (u32)i * 4u, 0.0f);
    // stage x0,y0 (enc layout: x at k 0..63, y at 64..127; part stride 768B)
    {
        int b = tid >> 3, k16 = (tid & 7) * 16;
        const float* s = ((k16 < 64) ? pre_x : pre_y) + (size_t)(bbase + b) * 64 + (k16 & 63);
        stage16(SB + OFF_U + (u32)b * UP, (u32)k16, s, 768u);
    }

    // biases in regs
    float ebias[4], sbias[4], cb[2];
#pragma unroll
    for (int m = 0; m < 2; m++)
#pragma unroll
        for (int rh = 0; rh < 2; rh++) {
            int j = warp * 32 + m * 16 + gg + rh * 8;
            ebias[m * 2 + rh] = b_ih[j] + b_hh[j];
            sbias[m * 2 + rh] = A_b[j] + B_b[j];
        }
    cb[0] = C_b[(warp & 3) * 16 + gg];
    cb[1] = C_b[(warp & 3) * 16 + gg + 8];
    __syncthreads();

    // ================= encoder =================
    for (int t = 0; t < 64; t++) {
        float acc[2][4][4] = {};
        gemm_g<12>(g_enc, SB, warp, lane, acc);
        __syncthreads();                       // all reads of old U done
        const bool last = (t == 63);
        const u32 hb = last ? 64u : 128u;      // h base slot (ssm vs enc layout)
        const u32 Pb = last ? 640u : 768u;     // part stride bytes
#pragma unroll
        for (int m = 0; m < 2; m++)
#pragma unroll
            for (int nt = 0; nt < 4; nt++)
#pragma unroll
                for (int r = 0; r < 4; r++) {
                    int j = warp * 32 + m * 16 + gg + (r >> 1) * 8;
                    int b = nt * 8 + tig * 2 + (r & 1);
                    float v = my_tanh(acc[m][nt][r] + ebias[m * 2 + (r >> 1)]);
                    put_duo(SB + OFF_U + (u32)b * UP, hb + (u32)j, v, Pb);
                }
        // stage next inputs
        if (!last) {
            int b = tid >> 3, k16 = (tid & 7) * 16;
            const float* s = ((k16 < 64) ? pre_x : pre_y) +
                             (size_t)(t + 1) * 4096 * 64 + (size_t)(bbase + b) * 64 + (k16 & 63);
            stage16(SB + OFF_U + (u32)b * UP, (u32)k16, s, 768u);
        } else {
            int b = tid >> 3, k16 = (tid & 7) * 16;
            if (k16 < 64) {
                const float* s = fwd_x + (size_t)(bbase + b) * 64 + k16;
                stage16(SB + OFF_U + (u32)b * UP, (u32)k16, s, 640u);
            }
        }
        __syncthreads();                       // new U visible
    }

    // ================= SSM + output projection =================
    for (int t = 0; t < 80; t++) {
        float acc[2][4][4] = {};
        gemm_g<10>(g_ssm, SB, warp, lane, acc);
        __syncthreads();
        // write h_t (ssm layout: h at slots 64.., part stride 640B)
#pragma unroll
        for (int m = 0; m < 2; m++)
#pragma unroll
            for (int nt = 0; nt < 4; nt++)
#pragma unroll
                for (int r = 0; r < 4; r++) {
                    int j = warp * 32 + m * 16 + gg + (r >> 1) * 8;
                    int b = nt * 8 + tig * 2 + (r & 1);
                    float v = acc[m][nt][r] + sbias[m * 2 + (r >> 1)];
                    put_duo(SB + OFF_U + (u32)b * UP, 64u + (u32)j, v, 640u);
                }
        __syncthreads();                       // h_t visible for C projection

        // C projection split across all 8 warps: j-tile = warp&3, n-half = warp>>2
        {
            const int jw = warp & 3, nh = warp >> 2;
            float accc[2][4] = {};
            const u32 bB = SB + OFF_U + (u32)(lane >> 2) * UP + (u32)(lane & 3) * 4u;
            const uint4* __restrict__ ap =
                (const uint4*)(g_cw + (u32)(jw * 512) + (u32)(lane * 16));
            uint4 Acur = __ldg(ap);            // chunk0 slab0
#pragma unroll 1
            for (int c = 0; c < 2; c++) {
#pragma unroll
                for (int sl = 0; sl < 16; sl++) {
                    uint4 Anext;
                    if (sl < 15)      Anext = __ldg(ap + (u32)c * 2048u + (u32)(sl + 1) * 128u);
                    else if (c == 0)  Anext = __ldg(ap + 2048u);
                    const u32* a0 = (const u32*)&Acur;
                    u32 su = (u32)c * 20u + 4u + (u32)sl;    // U h-region slabs
                    u32 bk = bB + su * 32u;
#pragma unroll
                    for (int h = 0; h < 2; h++) {
                        int nt = nh * 2 + h;
                        u32 b0, b1;
                        LDS32U(b0, bk + (u32)nt * (8u * UP));
                        LDS32U(b1, bk + (u32)nt * (8u * UP) + 16u);
                        MMA16816(accc[h], a0, b0, b1);
                    }
                    Acur = Anext;
                }
            }
            // epilogue: y -> gmem
            float* op = out + (size_t)t * 4096 * 64 + (size_t)bbase * 64;
#pragma unroll
            for (int h = 0; h < 2; h++)
#pragma unroll
                for (int r = 0; r < 4; r++) {
                    int o = jw * 16 + gg + (r >> 1) * 8;
                    int b = (nh * 2 + h) * 8 + tig * 2 + (r & 1);
                    op[(size_t)b * 64 + o] = accc[h][r] + cb[r >> 1];
                }
        }
        // stage x_{t+1} (all threads)
        if (t < 79) {
            int b = tid >> 3, k8 = (tid & 7) * 8;
            const float* s = fwd_x + (size_t)(t + 1) * 4096 * 64 + (size_t)(bbase + b) * 64 + k8;
            stage8(SB + OFF_U + (u32)b * UP, (u32)k8, s, 640u);
        }
        __syncthreads();                       // x staged + C-proj reads done
    }
}

extern "C" void kernel_launch(void* const* d_in, const int* in_sizes, int n_in,
                              void* d_out, int out_size) {
    const float* pre_x = (const float*)d_in[0];
    const float* pre_y = (const float*)d_in[1];
    const float* fwd_x = (const float*)d_in[2];
    const float* A_w   = (const float*)d_in[3];
    const float* A_b   = (const float*)d_in[4];
    const float* B_w   = (const float*)d_in[5];
    const float* B_b   = (const float*)d_in[6];
    const float* C_w   = (const float*)d_in[7];
    const float* C_b   = (const float*)d_in[8];
    const float* W_ih  = (const float*)d_in[9];
    const float* b_ih  = (const float*)d_in[10];
    const float* W_hh  = (const float*)d_in[11];
    const float* b_hh  = (const float*)d_in[12];
    float* out = (float*)d_out;

    prep<<<1536, 256>>>(A_w, B_w, C_w, W_ih, W_hh);
    cudaFuncSetAttribute(ss_main, cudaFuncAttributeMaxDynamicSharedMemorySize, SMEM_TOTAL);
    ss_main<<<128, 256, SMEM_TOTAL>>>(pre_x, pre_y, fwd_x, A_b, B_b, C_b,
                                      b_ih, b_hh, out);
}

// round 11
// speedup vs baseline: 2.0186x; 2.0186x over previous
#include <cuda_runtime.h>
#include <cuda_fp16.h>
#include <math.h>

typedef unsigned long long u64;
typedef unsigned int u32;
typedef unsigned short u16;

// -------- prepped fragment-order weight streams (fp16 hi/lo, 2-term split) --------
__device__ __align__(128) unsigned char g_enc[393216];  // 12 chunks x 32KB, Ktilde=768
__device__ __align__(128) unsigned char g_ssm[327680];  // 10 chunks x 32KB, Ktilde=640
__device__ __align__(128) unsigned char g_cw[65536];    //  2 chunks x 32KB, Ktilde=512

__device__ __forceinline__ u16 hf_hi(float w) { return __half_as_ushort(__float2half_rn(w)); }
__device__ __forceinline__ u16 hf_lo(float w) {
    float h = __half2float(__float2half_rn(w));
    return __half_as_ushort(__float2half_rn(w - h));
}

// One thread per output fp16. Layout: chunk(32KB) -> slab(8KB enc/ssm, 2KB C) ->
// block(512B, (warp,mtile)) -> lane(16B) -> 4 regs x f16x2, matching the PTX
// m16n8k16 A-fragment: reg r holds (row + (r&1)*8, k + (r>>1)*8 + h).
__global__ void prep(const float* __restrict__ A_w, const float* __restrict__ B_w,
                     const float* __restrict__ C_w, const float* __restrict__ W_ih,
                     const float* __restrict__ W_hh) {
    u32 e = blockIdx.x * 256u + threadIdx.x;
    u32 kind, pos;
    if (e < 196608u)      { kind = 0; pos = e * 2u; }
    else if (e < 360448u) { kind = 1; pos = (e - 196608u) * 2u; }
    else if (e < 393216u) { kind = 2; pos = (e - 360448u) * 2u; }
    else return;
    u32 chunk = pos >> 15, inch = pos & 32767u;
    u32 slab, w, m, r3;
    if (kind < 2) { slab = inch >> 13; u32 r2 = inch & 8191u; u32 blk = r2 >> 9; w = blk >> 1; m = blk & 1u; r3 = r2 & 511u; }
    else          { slab = inch >> 11; u32 r2 = inch & 2047u; w = r2 >> 9; m = 0; r3 = r2 & 511u; }
    u32 t = r3 >> 4, r4 = r3 & 15u, reg = r4 >> 2, h = (r4 & 3u) >> 1;
    u32 row = (t >> 2) + (reg & 1u) * 8u;
    u32 kl  = (t & 3u) * 2u + (reg >> 1) * 8u + h;
    float src; u32 p;
    if (kind == 0) {
        u32 j = w * 32u + m * 16u + row;
        u32 kt = (chunk * 4u + slab) * 16u + kl;
        p = kt / 384u; u32 kk = kt % 384u;
        src = (kk < 128u) ? W_ih[j * 128u + kk] : W_hh[j * 256u + kk - 128u];
        *(u16*)(g_enc + pos) = p ? hf_lo(src) : hf_hi(src);
    } else if (kind == 1) {
        u32 j = w * 32u + m * 16u + row;
        u32 kt = (chunk * 4u + slab) * 16u + kl;
        p = kt / 320u; u32 kk = kt % 320u;
        src = (kk < 64u) ? B_w[j * 64u + kk] : A_w[j * 256u + kk - 64u];
        *(u16*)(g_ssm + pos) = p ? hf_lo(src) : hf_hi(src);
    } else {
        u32 o = w * 16u + row;
        u32 g4 = chunk * 16u + slab;
        p = g4 >> 4;
        u32 k = (g4 & 15u) * 16u + kl;        // 0..255
        src = C_w[o * 256u + k];
        *(u16*)(g_cw + pos) = p ? hf_lo(src) : hf_hi(src);
    }
}

// ---------------- PTX helpers ----------------
__device__ __forceinline__ u32 smem_u32(const void* p) {
    u32 a;
    asm("{ .reg .u64 t; cvta.to.shared.u64 t, %1; cvt.u32.u64 %0, t; }" : "=r"(a) : "l"(p));
    return a;
}
#define STS16(addr, v)  asm volatile("st.shared.u16 [%0], %1;" :: "r"(addr), "h"(v))
#define STS32(addr, f)  asm volatile("st.shared.f32 [%0], %1;" :: "r"(addr), "f"(f))
#define STSU32(addr, v) asm volatile("st.shared.u32 [%0], %1;" :: "r"(addr), "r"(v))
#define LDS32U(r, addr) asm volatile("ld.shared.u32 %0, [%1];" : "=r"(r) : "r"(addr))

#define MMA16816(c, a, b0, b1) \
    asm volatile("mma.sync.aligned.m16n8k16.row.col.f32.f16.f16.f32 " \
                 "{%0,%1,%2,%3},{%4,%5,%6,%7},{%8,%9},{%0,%1,%2,%3};" \
                 : "+f"((c)[0]), "+f"((c)[1]), "+f"((c)[2]), "+f"((c)[3]) \
                 : "r"((a)[0]), "r"((a)[1]), "r"((a)[2]), "r"((a)[3]), "r"(b0), "r"(b1))

__device__ __forceinline__ float my_tanh(float x) {
    float ax = fabsf(x);
    float e  = __expf(2.0f * ax);
    float r  = 1.0f - 2.0f / (e + 1.0f);
    return copysignf(r, x);
}

// ---------------- smem layout: U only ----------------
constexpr u32 UP = 1552;                 // U row pitch bytes (UP%128==16 -> conflict-free)
constexpr u32 OFF_U = 0;
constexpr u32 SMEM_TOTAL = 32 * UP;      // 49664

// dual-slot U write: hi at k, lo at k+P (Pb = part stride bytes)
__device__ __forceinline__ void put_duo(u32 ub, u32 k, float v, u32 Pb) {
    __half hb = __float2half_rn(v);
    u16 hi = __half_as_ushort(hb);
    u16 lo = __half_as_ushort(__float2half_rn(v - __half2float(hb)));
    u32 a = ub + k * 2u;
    STS16(a, hi); STS16(a + Pb, lo);
}

// stage 16 consecutive k-slots for one batch row: vector LDG + paired STS32
__device__ __forceinline__ void stage16(u32 ub, u32 k0, const float* s, u32 Pb) {
    float v[16];
    const float4* s4 = (const float4*)s;
#pragma unroll
    for (int q = 0; q < 4; q++) {
        float4 f = __ldg(s4 + q);
        v[q * 4] = f.x; v[q * 4 + 1] = f.y; v[q * 4 + 2] = f.z; v[q * 4 + 3] = f.w;
    }
#pragma unroll
    for (int i = 0; i < 16; i += 2) {
        __half a = __float2half_rn(v[i]), b = __float2half_rn(v[i + 1]);
        __half al = __float2half_rn(v[i] - __half2float(a));
        __half bl = __float2half_rn(v[i + 1] - __half2float(b));
        u32 hi = (u32)__half_as_ushort(a) | ((u32)__half_as_ushort(b) << 16);
        u32 lo = (u32)__half_as_ushort(al) | ((u32)__half_as_ushort(bl) << 16);
        u32 ad = ub + (k0 + (u32)i) * 2u;
        STSU32(ad, hi); STSU32(ad + Pb, lo);
    }
}
__device__ __forceinline__ void stage8(u32 ub, u32 k0, const float* s, u32 Pb) {
    float v[8];
    const float4* s4 = (const float4*)s;
#pragma unroll
    for (int q = 0; q < 2; q++) {
        float4 f = __ldg(s4 + q);
        v[q * 4] = f.x; v[q * 4 + 1] = f.y; v[q * 4 + 2] = f.z; v[q * 4 + 3] = f.w;
    }
#pragma unroll
    for (int i = 0; i < 8; i += 2) {
        __half a = __float2half_rn(v[i]), b = __float2half_rn(v[i + 1]);
        __half al = __float2half_rn(v[i] - __half2float(a));
        __half bl = __float2half_rn(v[i + 1] - __half2float(b));
        u32 hi = (u32)__half_as_ushort(a) | ((u32)__half_as_ushort(b) << 16);
        u32 lo = (u32)__half_as_ushort(al) | ((u32)__half_as_ushort(bl) << 16);
        u32 ad = ub + (k0 + (u32)i) * 2u;
        STSU32(ad, hi); STSU32(ad + Pb, lo);
    }
}

// ---- spill-free chunk helpers: statically-named register buffers only ----
__device__ __forceinline__ void chunk_load(uint4 (&A)[8], const uint4* __restrict__ ap) {
#pragma unroll
    for (int sl = 0; sl < 4; sl++) {
        A[sl * 2]     = __ldg(ap + sl * 512);
        A[sl * 2 + 1] = __ldg(ap + sl * 512 + 32);
    }
}
__device__ __forceinline__ void chunk_compute(const uint4 (&A)[8], u32 bB, u32& kt,
                                              float acc[2][4][4]) {
#pragma unroll
    for (int sl = 0; sl < 4; sl++) {
        u32 bk = bB + kt * 2u;
        u32 b0[4], b1[4];
#pragma unroll
        for (int nt = 0; nt < 4; nt++) {
            LDS32U(b0[nt], bk + (u32)nt * (8u * UP));
            LDS32U(b1[nt], bk + (u32)nt * (8u * UP) + 16u);
        }
        const u32* a0 = (const u32*)&A[sl * 2];
        const u32* a1 = (const u32*)&A[sl * 2 + 1];
#pragma unroll
        for (int nt = 0; nt < 4; nt++) {
            MMA16816(acc[0][nt], a0, b0[nt], b1[nt]);
            MMA16816(acc[1][nt], a1, b0[nt], b1[nt]);
        }
        kt += 16;
    }
}

// main GEMM: A-frags via LDG.128 from the L2-resident prepped stream with
// explicit ping-pong register double-buffering (NCH must be even).
template <int NCH>
__device__ __forceinline__ void gemm_g(const unsigned char* __restrict__ gw,
                                       u32 SB, int warp, int lane,
                                       float acc[2][4][4]) {
    static_assert(NCH % 2 == 0, "NCH even");
    const u32 bB = SB + OFF_U + (u32)(lane >> 2) * UP + (u32)(lane & 3) * 4u;
    const uint4* __restrict__ ap =
        (const uint4*)(gw + (u32)(warp * 1024) + (u32)(lane * 16));
    uint4 A0[8], A1[8];
    chunk_load(A0, ap);
    u32 kt = 0;
#pragma unroll 1
    for (int c = 0; c < NCH; c += 2) {
        chunk_load(A1, ap + (u32)(c + 1) * 2048u);
        chunk_compute(A0, bB, kt, acc);
        if (c + 2 < NCH) chunk_load(A0, ap + (u32)(c + 2) * 2048u);
        chunk_compute(A1, bB, kt, acc);
    }
}

__global__ __launch_bounds__(256, 1) void ss_main(
    const float* __restrict__ pre_x, const float* __restrict__ pre_y,
    const float* __restrict__ fwd_x,
    const float* __restrict__ A_b, const float* __restrict__ B_b,
    const float* __restrict__ C_b, const float* __restrict__ b_ih,
    const float* __restrict__ b_hh, float* __restrict__ out)
{
    extern __shared__ char smraw[];
    const u32 SB = smem_u32(smraw);
    const int tid = threadIdx.x, lane = tid & 31, warp = tid >> 5;
    const int bbase = blockIdx.x * 32;
    const int gg = lane >> 2, tig = lane & 3;

    // zero U
    for (int i = tid; i < (int)(32 * UP / 4); i += 256) STS32(SB + OFF_U + (u32)i * 4u, 0.0f);
    // stage x0,y0 (enc layout: x at k 0..63, y at 64..127; part stride 768B)
    {
        int b = tid >> 3, k16 = (tid & 7) * 16;
        const float* s = ((k16 < 64) ? pre_x : pre_y) + (size_t)(bbase + b) * 64 + (k16 & 63);
        stage16(SB + OFF_U + (u32)b * UP, (u32)k16, s, 768u);
    }

    // biases in regs
    float ebias[4], sbias[4], cb[2];
#pragma unroll
    for (int m = 0; m < 2; m++)
#pragma unroll
        for (int rh = 0; rh < 2; rh++) {
            int j = warp * 32 + m * 16 + gg + rh * 8;
            ebias[m * 2 + rh] = b_ih[j] + b_hh[j];
            sbias[m * 2 + rh] = A_b[j] + B_b[j];
        }
    cb[0] = C_b[(warp & 3) * 16 + gg];
    cb[1] = C_b[(warp & 3) * 16 + gg + 8];
    __syncthreads();

    // ================= encoder =================
    for (int t = 0; t < 64; t++) {
        float acc[2][4][4] = {};
        gemm_g<12>(g_enc, SB, warp, lane, acc);
        __syncthreads();                       // all reads of old U done
        const bool last = (t == 63);
        const u32 hb = last ? 64u : 128u;      // h base slot (ssm vs enc layout)
        const u32 Pb = last ? 640u : 768u;     // part stride bytes
#pragma unroll
        for (int m = 0; m < 2; m++)
#pragma unroll
            for (int nt = 0; nt < 4; nt++)
#pragma unroll
                for (int r = 0; r < 4; r++) {
                    int j = warp * 32 + m * 16 + gg + (r >> 1) * 8;
                    int b = nt * 8 + tig * 2 + (r & 1);
                    float v = my_tanh(acc[m][nt][r] + ebias[m * 2 + (r >> 1)]);
                    put_duo(SB + OFF_U + (u32)b * UP, hb + (u32)j, v, Pb);
                }
        // stage next inputs
        if (!last) {
            int b = tid >> 3, k16 = (tid & 7) * 16;
            const float* s = ((k16 < 64) ? pre_x : pre_y) +
                             (size_t)(t + 1) * 4096 * 64 + (size_t)(bbase + b) * 64 + (k16 & 63);
            stage16(SB + OFF_U + (u32)b * UP, (u32)k16, s, 768u);
        } else {
            int b = tid >> 3, k16 = (tid & 7) * 16;
            if (k16 < 64) {
                const float* s = fwd_x + (size_t)(bbase + b) * 64 + k16;
                stage16(SB + OFF_U + (u32)b * UP, (u32)k16, s, 640u);
            }
        }
        __syncthreads();                       // new U visible
    }

    // ================= SSM + output projection =================
    for (int t = 0; t < 80; t++) {
        float acc[2][4][4] = {};
        gemm_g<10>(g_ssm, SB, warp, lane, acc);
        __syncthreads();
        // write h_t (ssm layout: h at slots 64.., part stride 640B)
#pragma unroll
        for (int m = 0; m < 2; m++)
#pragma unroll
            for (int nt = 0; nt < 4; nt++)
#pragma unroll
                for (int r = 0; r < 4; r++) {
                    int j = warp * 32 + m * 16 + gg + (r >> 1) * 8;
                    int b = nt * 8 + tig * 2 + (r & 1);
                    float v = acc[m][nt][r] + sbias[m * 2 + (r >> 1)];
                    put_duo(SB + OFF_U + (u32)b * UP, 64u + (u32)j, v, 640u);
                }
        __syncthreads();                       // h_t visible for C projection

        // C projection split across all 8 warps: j-tile = warp&3, n-half = warp>>2
        {
            const int jw = warp & 3, nh = warp >> 2;
            float accc[2][4] = {};
            const u32 bB = SB + OFF_U + (u32)(lane >> 2) * UP + (u32)(lane & 3) * 4u;
            const uint4* __restrict__ ap =
                (const uint4*)(g_cw + (u32)(jw * 512) + (u32)(lane * 16));
            uint4 Acur = __ldg(ap);            // chunk0 slab0
#pragma unroll 1
            for (int c = 0; c < 2; c++) {
#pragma unroll
                for (int sl = 0; sl < 16; sl++) {
                    uint4 Anext;
                    if (sl < 15)      Anext = __ldg(ap + (u32)c * 2048u + (u32)(sl + 1) * 128u);
                    else if (c == 0)  Anext = __ldg(ap + 2048u);
                    const u32* a0 = (const u32*)&Acur;
                    u32 su = (u32)c * 20u + 4u + (u32)sl;    // U h-region slabs
                    u32 bk = bB + su * 32u;
#pragma unroll
                    for (int h = 0; h < 2; h++) {
                        int nt = nh * 2 + h;
                        u32 b0, b1;
                        LDS32U(b0, bk + (u32)nt * (8u * UP));
                        LDS32U(b1, bk + (u32)nt * (8u * UP) + 16u);
                        MMA16816(accc[h], a0, b0, b1);
                    }
                    Acur = Anext;
                }
            }
            // epilogue: y -> gmem
            float* op = out + (size_t)t * 4096 * 64 + (size_t)bbase * 64;
#pragma unroll
            for (int h = 0; h < 2; h++)
#pragma unroll
                for (int r = 0; r < 4; r++) {
                    int o = jw * 16 + gg + (r >> 1) * 8;
                    int b = (nh * 2 + h) * 8 + tig * 2 + (r & 1);
                    op[(size_t)b * 64 + o] = accc[h][r] + cb[r >> 1];
                }
        }
        // stage x_{t+1} (all threads)
        if (t < 79) {
            int b = tid >> 3, k8 = (tid & 7) * 8;
            const float* s = fwd_x + (size_t)(t + 1) * 4096 * 64 + (size_t)(bbase + b) * 64 + k8;
            stage8(SB + OFF_U + (u32)b * UP, (u32)k8, s, 640u);
        }
        __syncthreads();                       // x staged + C-proj reads done
    }
}

extern "C" void kernel_launch(void* const* d_in, const int* in_sizes, int n_in,
                              void* d_out, int out_size) {
    const float* pre_x = (const float*)d_in[0];
    const float* pre_y = (const float*)d_in[1];
    const float* fwd_x = (const float*)d_in[2];
    const float* A_w   = (const float*)d_in[3];
    const float* A_b   = (const float*)d_in[4];
    const float* B_w   = (const float*)d_in[5];
    const float* B_b   = (const float*)d_in[6];
    const float* C_w   = (const float*)d_in[7];
    const float* C_b   = (const float*)d_in[8];
    const float* W_ih  = (const float*)d_in[9];
    const float* b_ih  = (const float*)d_in[10];
    const float* W_hh  = (const float*)d_in[11];
    const float* b_hh  = (const float*)d_in[12];
    float* out = (float*)d_out;

    prep<<<1536, 256>>>(A_w, B_w, C_w, W_ih, W_hh);
    cudaFuncSetAttribute(ss_main, cudaFuncAttributeMaxDynamicSharedMemorySize, SMEM_TOTAL);
    ss_main<<<128, 256, SMEM_TOTAL>>>(pre_x, pre_y, fwd_x, A_b, B_b, C_b,
                                      b_ih, b_hh, out);
}